// round 5
// baseline (speedup 1.0000x reference)
#include <cuda_runtime.h>
#include <cuda_bf16.h>

// ---------------------------------------------------------------------------
// Problem constants
// ---------------------------------------------------------------------------
#define NPIX 2304      // N = 48*48
#define CDIM 128       // channels
#define NH   4         // heads
#define HC   32        // head channels
#define NCLUST 16      // clusters
#define HID  256       // mlp hidden = 2C

// ---------------------------------------------------------------------------
// Device scratch (allocation-free rule: __device__ globals)
// ---------------------------------------------------------------------------
__device__ float g_q[NPIX * CDIM];
__device__ float g_k[NPIX * CDIM];
__device__ float g_v[NPIX * CDIM];
__device__ float g_cacc[NCLUST * CDIM];
__device__ float g_ccnt[NCLUST];
__device__ float g_centers[NCLUST * CDIM];
__device__ float g_attn[NPIX * CDIM];
__device__ float g_h1[NPIX * HID];
__device__ float g_rs1[NPIX * CDIM];
__device__ float g_h2[NPIX * HID];

// ---------------------------------------------------------------------------
// Generic tiled GEMM:  C = act(A @ W + b) (+ res), optional transposed A read
// (A stored [K][M], i.e. channel-major image) and transposed C write.
// BM=64, BN=64, BK=16, 256 threads, 4x4 register microtile.
// ---------------------------------------------------------------------------
#define BM 64
#define BN 64
#define BK 16

template <bool TRANSA, bool LEAKY, bool TRANSOUT>
__global__ void __launch_bounds__(256) gemm_k(
    const float* __restrict__ A, const float* __restrict__ W,
    const float* __restrict__ bias, const float* __restrict__ res,
    float* __restrict__ C, int M, int Kd, int Nout)
{
    __shared__ float As[BK][BM + 4];
    __shared__ float Ws[BK][BN + 4];

    const int tid = threadIdx.x;
    const int tx = tid & 15;   // -> n
    const int ty = tid >> 4;   // -> m
    const int m0 = blockIdx.y * BM;
    const int n0 = blockIdx.x * BN;

    float acc[4][4] = {};

    for (int k0 = 0; k0 < Kd; k0 += BK) {
        if (TRANSA) {
            #pragma unroll
            for (int idx = tid; idx < BM * BK; idx += 256) {
                int kk = idx >> 6, r = idx & 63;
                As[kk][r] = A[(k0 + kk) * M + m0 + r];
            }
        } else {
            #pragma unroll
            for (int idx = tid; idx < BM * BK; idx += 256) {
                int r = idx >> 4, kk = idx & 15;
                As[kk][r] = A[(m0 + r) * Kd + k0 + kk];
            }
        }
        #pragma unroll
        for (int idx = tid; idx < BK * BN; idx += 256) {
            int kk = idx >> 6, c = idx & 63;
            Ws[kk][c] = W[(k0 + kk) * Nout + n0 + c];
        }
        __syncthreads();

        #pragma unroll
        for (int kk = 0; kk < BK; kk++) {
            float4 a4 = *(const float4*)&As[kk][ty * 4];
            float4 b4 = *(const float4*)&Ws[kk][tx * 4];
            float av[4] = {a4.x, a4.y, a4.z, a4.w};
            float bv[4] = {b4.x, b4.y, b4.z, b4.w};
            #pragma unroll
            for (int i = 0; i < 4; i++)
                #pragma unroll
                for (int j = 0; j < 4; j++)
                    acc[i][j] += av[i] * bv[j];
        }
        __syncthreads();
    }

    const int mb = m0 + ty * 4;
    const int nb = n0 + tx * 4;
    float4 bq = *(const float4*)&bias[nb];
    float bvv[4] = {bq.x, bq.y, bq.z, bq.w};

    if (!TRANSOUT) {
        #pragma unroll
        for (int i = 0; i < 4; i++) {
            float4 o;
            float* op = (float*)&o;
            float rr[4] = {0.f, 0.f, 0.f, 0.f};
            if (res) {
                float4 r4 = *(const float4*)&res[(mb + i) * Nout + nb];
                rr[0] = r4.x; rr[1] = r4.y; rr[2] = r4.z; rr[3] = r4.w;
            }
            #pragma unroll
            for (int j = 0; j < 4; j++) {
                float val = acc[i][j] + bvv[j];
                if (LEAKY) val = val > 0.f ? val : 0.01f * val;
                val += rr[j];
                op[j] = val;
            }
            *(float4*)&C[(mb + i) * Nout + nb] = o;
        }
    } else {
        #pragma unroll
        for (int j = 0; j < 4; j++) {
            float4 o;
            float* op = (float*)&o;
            #pragma unroll
            for (int i = 0; i < 4; i++) {
                float val = acc[i][j] + bvv[j];
                if (LEAKY) val = val > 0.f ? val : 0.01f * val;
                if (res) val += res[(mb + i) * Nout + nb + j];
                op[i] = val;
            }
            *(float4*)&C[(nb + j) * M + mb] = o;
        }
    }
}

// ---------------------------------------------------------------------------
// Cluster centers: zero -> accumulate (16 blocks x 128 threads) -> normalize
// ---------------------------------------------------------------------------
__global__ void centers_zero_k()
{
    int t = blockIdx.x * blockDim.x + threadIdx.x;
    if (t < NCLUST * CDIM) g_cacc[t] = 0.f;
    if (t < NCLUST) g_ccnt[t] = 0.f;
}

__global__ void __launch_bounds__(128) centers_accum_k(const int* __restrict__ labels)
{
    __shared__ float sacc[NCLUST * CDIM];
    const int c = threadIdx.x;
    #pragma unroll
    for (int kk = 0; kk < NCLUST; kk++) sacc[kk * CDIM + c] = 0.f;

    const int n0 = blockIdx.x * (NPIX / 16);
    float cnt = 0.f;
    for (int n = n0; n < n0 + (NPIX / 16); n++) {
        int lab = labels[n];
        sacc[lab * CDIM + c] += g_k[n * CDIM + c];
        if (c == lab) cnt += 1.f;
    }
    #pragma unroll
    for (int kk = 0; kk < NCLUST; kk++)
        atomicAdd(&g_cacc[kk * CDIM + c], sacc[kk * CDIM + c]);
    if (c < NCLUST) atomicAdd(&g_ccnt[c], cnt);
}

__global__ void centers_norm_k()
{
    int t = blockIdx.x * blockDim.x + threadIdx.x;
    if (t < NCLUST * CDIM) {
        int kk = t >> 7;
        g_centers[t] = g_cacc[t] / (g_ccnt[kk] + 1e-6f);
    }
}

// ---------------------------------------------------------------------------
// Attention: block = (32-query tile, head). Online softmax over 64-key tiles.
// Cross-cluster scores = center_score * pc (cheap, uniform); same-cluster
// pairs compacted into a list and processed warp-coherently (8 thr / pair).
// ---------------------------------------------------------------------------
__global__ void __launch_bounds__(256) attn_k(
    const float* __restrict__ q, const float* __restrict__ k,
    const float* __restrict__ v, const float* __restrict__ centers,
    const float* __restrict__ pc, const int* __restrict__ labels,
    float* __restrict__ out)
{
    const int h  = blockIdx.y;
    const int i0 = blockIdx.x * 32;
    const int tid = threadIdx.x;

    __shared__ float qs[32][32];
    __shared__ float cks[16][32];
    __shared__ float css[32][16];
    __shared__ float ks[64][32];
    __shared__ float vs[64][32];
    __shared__ float pcs[32][64];
    __shared__ float sS[32][64];
    __shared__ unsigned short pairbuf[2048];
    __shared__ int   labq[32];
    __shared__ int   labj[64];
    __shared__ float mbuf[32];
    __shared__ float lbuf[32];
    __shared__ int   nIntra;

    // prologue: q tile + center head-slice + query labels
    #pragma unroll
    for (int idx = tid; idx < 1024; idx += 256) {
        int qi = idx >> 5, d = idx & 31;
        qs[qi][d] = q[(i0 + qi) * CDIM + h * HC + d];
    }
    #pragma unroll
    for (int idx = tid; idx < 512; idx += 256) {
        int kk = idx >> 5, d = idx & 31;
        cks[kk][d] = centers[kk * CDIM + h * HC + d];
    }
    if (tid < 32) {
        labq[tid] = labels[i0 + tid];
        mbuf[tid] = -1e30f;
        lbuf[tid] = 0.f;
    }
    __syncthreads();

    // center scores css[qi][kk] = q_i . center_kk (head slice)
    for (int r = tid; r < 512; r += 256) {
        int qi = r >> 4, kk = r & 15;
        float s = 0.f;
        #pragma unroll
        for (int d = 0; d < 32; d++) s += qs[qi][d] * cks[kk][d];
        css[qi][kk] = s;
    }

    const int qi = tid >> 3;   // 0..31
    const int dg = tid & 7;    // 0..7 -> d = dg*4..dg*4+3
    float4 acc = {0.f, 0.f, 0.f, 0.f};
    const float invScale = 0.17677669529663687f;  // 1/sqrt(32)

    for (int j0 = 0; j0 < NPIX; j0 += 64) {
        __syncthreads();   // previous tile PV done before overwriting tiles

        #pragma unroll
        for (int idx = tid; idx < 2048; idx += 256) {
            int j = idx >> 5, d = idx & 31;
            ks[j][d] = k[(j0 + j) * CDIM + h * HC + d];
            vs[j][d] = v[(j0 + j) * CDIM + h * HC + d];
        }
        #pragma unroll
        for (int idx = tid; idx < 2048; idx += 256) {
            int qq = idx >> 6, jj = idx & 63;
            pcs[qq][jj] = pc[(i0 + qq) * NPIX + j0 + jj];
        }
        if (tid < 64) labj[tid] = labels[j0 + tid];
        if (tid == 0) nIntra = 0;
        __syncthreads();

        // inter scores (uniform) + compact intra pairs
        #pragma unroll
        for (int idx = tid; idx < 2048; idx += 256) {
            int qq = idx >> 6, jj = idx & 63;
            int lj = labj[jj];
            if (lj == labq[qq]) {
                int pos = atomicAdd(&nIntra, 1);
                pairbuf[pos] = (unsigned short)((qq << 6) | jj);
            } else {
                sS[qq][jj] = css[qq][lj] * pcs[qq][jj] * invScale;
            }
        }
        __syncthreads();

        // intra pairs: 8 threads per pair, shuffle-reduced dot32
        const int nI = nIntra;
        for (int base = 0; base < nI; base += 32) {
            int pi = base + (tid >> 3);
            int g  = tid & 7;
            float partial = 0.f;
            int pq = 0, pj = 0;
            if (pi < nI) {
                int code = pairbuf[pi];
                pq = code >> 6; pj = code & 63;
                float4 a = *(const float4*)&qs[pq][g * 4];
                float4 b = *(const float4*)&ks[pj][g * 4];
                partial = a.x * b.x + a.y * b.y + a.z * b.z + a.w * b.w;
            }
            partial += __shfl_xor_sync(0xffffffffu, partial, 1);
            partial += __shfl_xor_sync(0xffffffffu, partial, 2);
            partial += __shfl_xor_sync(0xffffffffu, partial, 4);
            if (pi < nI && g == 0) sS[pq][pj] = partial * invScale;
        }
        __syncthreads();

        // online softmax update (8 threads per query, same-warp group)
        float mloc = -1e30f;
        #pragma unroll
        for (int r = 0; r < 8; r++) mloc = fmaxf(mloc, sS[qi][dg * 8 + r]);
        mloc = fmaxf(mloc, __shfl_xor_sync(0xffffffffu, mloc, 1));
        mloc = fmaxf(mloc, __shfl_xor_sync(0xffffffffu, mloc, 2));
        mloc = fmaxf(mloc, __shfl_xor_sync(0xffffffffu, mloc, 4));
        float mold = mbuf[qi];
        float mnew = fmaxf(mold, mloc);
        float factor = __expf(mold - mnew);
        float psum = 0.f;
        #pragma unroll
        for (int r = 0; r < 8; r++) {
            float p = __expf(sS[qi][dg * 8 + r] - mnew);
            sS[qi][dg * 8 + r] = p;
            psum += p;
        }
        psum += __shfl_xor_sync(0xffffffffu, psum, 1);
        psum += __shfl_xor_sync(0xffffffffu, psum, 2);
        psum += __shfl_xor_sync(0xffffffffu, psum, 4);
        if (dg == 0) {
            mbuf[qi] = mnew;
            lbuf[qi] = lbuf[qi] * factor + psum;
        }
        __syncwarp();

        // PV accumulate
        acc.x *= factor; acc.y *= factor; acc.z *= factor; acc.w *= factor;
        #pragma unroll 8
        for (int jj = 0; jj < 64; jj++) {
            float p = sS[qi][jj];
            float4 vv = *(const float4*)&vs[jj][dg * 4];
            acc.x += p * vv.x; acc.y += p * vv.y;
            acc.z += p * vv.z; acc.w += p * vv.w;
        }
    }

    __syncthreads();
    float linv = 1.0f / lbuf[qi];
    float4 o = {acc.x * linv, acc.y * linv, acc.z * linv, acc.w * linv};
    *(float4*)&out[(i0 + qi) * CDIM + h * HC + dg * 4] = o;
}

// ---------------------------------------------------------------------------
// Host orchestration
// ---------------------------------------------------------------------------
extern "C" void kernel_launch(void* const* d_in, const int* in_sizes, int n_in,
                              void* d_out, int out_size)
{
    // Input order detection: dict order has labels (2304 ints) at index 4;
    // signature order puts labels last (index 18).
    const bool dictOrder = (in_sizes[4] == NPIX);
    const int wb = dictOrder ? 5 : 4;

    const float* q_img = (const float*)d_in[0];
    const float* k_img = (const float*)d_in[1];
    const float* v_img = (const float*)d_in[2];
    const float* pc    = (const float*)d_in[3];
    const int*   labels = (const int*)d_in[dictOrder ? 4 : 18];

    const float* wq  = (const float*)d_in[wb + 0];
    const float* bq  = (const float*)d_in[wb + 1];
    const float* wk  = (const float*)d_in[wb + 2];
    const float* bk  = (const float*)d_in[wb + 3];
    const float* wv  = (const float*)d_in[wb + 4];
    const float* bv  = (const float*)d_in[wb + 5];
    const float* w1a = (const float*)d_in[wb + 6];
    const float* b1a = (const float*)d_in[wb + 7];
    const float* w1b = (const float*)d_in[wb + 8];
    const float* b1b = (const float*)d_in[wb + 9];
    const float* w2a = (const float*)d_in[wb + 10];
    const float* b2a = (const float*)d_in[wb + 11];
    const float* w2b = (const float*)d_in[wb + 12];
    const float* b2b = (const float*)d_in[wb + 13];
    float* out = (float*)d_out;

    void* p;
    cudaGetSymbolAddress(&p, g_q);       float* pq  = (float*)p;
    cudaGetSymbolAddress(&p, g_k);       float* pk  = (float*)p;
    cudaGetSymbolAddress(&p, g_v);       float* pv  = (float*)p;
    cudaGetSymbolAddress(&p, g_centers); float* pce = (float*)p;
    cudaGetSymbolAddress(&p, g_attn);    float* pat = (float*)p;
    cudaGetSymbolAddress(&p, g_h1);      float* ph1 = (float*)p;
    cudaGetSymbolAddress(&p, g_rs1);     float* pr1 = (float*)p;
    cudaGetSymbolAddress(&p, g_h2);      float* ph2 = (float*)p;

    dim3 blk(256);
    dim3 gProj(CDIM / BN, NPIX / BM);   // (2, 36)
    dim3 gHid(HID / BN, NPIX / BM);     // (4, 36)

    // projections (img is channel-major -> TRANSA read)
    gemm_k<true, false, false><<<gProj, blk>>>(q_img, wq, bq, nullptr, pq, NPIX, CDIM, CDIM);
    gemm_k<true, false, false><<<gProj, blk>>>(k_img, wk, bk, nullptr, pk, NPIX, CDIM, CDIM);
    gemm_k<true, false, false><<<gProj, blk>>>(v_img, wv, bv, nullptr, pv, NPIX, CDIM, CDIM);

    // cluster centers from projected k
    centers_zero_k<<<8, 256>>>();
    centers_accum_k<<<16, 128>>>(labels);
    centers_norm_k<<<8, 256>>>();

    // attention
    attn_k<<<dim3(NPIX / 32, NH), blk>>>(pq, pk, pv, pce, pc, labels, pat);

    // mlp_1 with residual v, mlp_2 with residual rs1 (transposed final write)
    gemm_k<false, true,  false><<<gHid,  blk>>>(pat, w1a, b1a, nullptr, ph1, NPIX, CDIM, HID);
    gemm_k<false, false, false><<<gProj, blk>>>(ph1, w1b, b1b, pv,      pr1, NPIX, HID, CDIM);
    gemm_k<false, true,  false><<<gHid,  blk>>>(pr1, w2a, b2a, nullptr, ph2, NPIX, CDIM, HID);
    gemm_k<false, false, true ><<<gProj, blk>>>(ph2, w2b, b2b, pr1,     out, NPIX, HID, CDIM);
}

// round 7
// speedup vs baseline: 1.0623x; 1.0623x over previous
#include <cuda_runtime.h>
#include <cuda_bf16.h>

// ---------------------------------------------------------------------------
// Problem constants
// ---------------------------------------------------------------------------
#define NPIX 2304      // N = 48*48
#define CDIM 128       // channels
#define NH   4         // heads
#define HC   32        // head channels
#define NCLUST 16      // clusters
#define HID  256       // mlp hidden = 2C

// ---------------------------------------------------------------------------
// Packed fp32x2 helpers (sm_100+: fma.rn.f32x2 — exact fp32 arithmetic)
// ---------------------------------------------------------------------------
__device__ __forceinline__ unsigned long long pack2(float x, float y) {
    unsigned long long r;
    asm("mov.b64 %0, {%1, %2};" : "=l"(r) : "f"(x), "f"(y));
    return r;
}
__device__ __forceinline__ void unpack2(unsigned long long v, float& x, float& y) {
    asm("mov.b64 {%0, %1}, %2;" : "=f"(x), "=f"(y) : "l"(v));
}
__device__ __forceinline__ void ffma2(unsigned long long& d,
                                      unsigned long long a, unsigned long long b) {
    asm("fma.rn.f32x2 %0, %1, %2, %0;" : "+l"(d) : "l"(a), "l"(b));
}
__device__ __forceinline__ unsigned long long mul2(unsigned long long a,
                                                   unsigned long long b) {
    unsigned long long r;
    asm("mul.rn.f32x2 %0, %1, %2;" : "=l"(r) : "l"(a), "l"(b));
    return r;
}

// ---------------------------------------------------------------------------
// Device scratch (allocation-free rule: __device__ globals; zero at load)
// ---------------------------------------------------------------------------
__device__ float g_q[NPIX * CDIM];
__device__ float g_k[NPIX * CDIM];
__device__ float g_v[NPIX * CDIM];
__device__ float g_cacc[NCLUST * CDIM];   // must be zero at entry of each run;
                                          // centers_norm_k re-zeroes it.
__device__ float g_centers[NCLUST * CDIM];
__device__ float g_attn[NPIX * CDIM];
__device__ float g_h1[NPIX * HID];
__device__ float g_rs1[NPIX * CDIM];
__device__ float g_h2[NPIX * HID];

// ---------------------------------------------------------------------------
// Tiled GEMM body:  C = act(A @ W + b) (+ res); BM=64, BN=64, BK=16,
// 256 threads, 4x4 microtile, f32x2 packed FMA inner loop.
// ---------------------------------------------------------------------------
#define BM 64
#define BN 64
#define BK 16

template <bool TRANSA, bool LEAKY, bool TRANSOUT>
__device__ __forceinline__ void gemm_body(
    const float* __restrict__ A, const float* __restrict__ W,
    const float* __restrict__ bias, const float* __restrict__ res,
    float* __restrict__ C, int M, int Kd, int Nout)
{
    __shared__ __align__(16) float As[BK][BM + 4];
    __shared__ __align__(16) float Ws[BK][BN + 4];

    const int tid = threadIdx.x;
    const int tx = tid & 15;   // -> n
    const int ty = tid >> 4;   // -> m
    const int m0 = blockIdx.y * BM;
    const int n0 = blockIdx.x * BN;

    unsigned long long acc2[4][2] = {};   // 4 rows x (2 packed pairs)

    for (int k0 = 0; k0 < Kd; k0 += BK) {
        if (TRANSA) {
            // A stored [K][M]: row kk has contiguous m — float4 copy
            int kk = tid >> 4, r4 = tid & 15;
            *(float4*)&As[kk][r4 * 4] =
                *(const float4*)&A[(k0 + kk) * M + m0 + r4 * 4];
        } else {
            // A stored [M][K]: contiguous kk — float4 load, scattered store
            int r = tid & 63, kq = tid >> 6;
            float4 g = *(const float4*)&A[(m0 + r) * Kd + k0 + kq * 4];
            As[kq * 4 + 0][r] = g.x;
            As[kq * 4 + 1][r] = g.y;
            As[kq * 4 + 2][r] = g.z;
            As[kq * 4 + 3][r] = g.w;
        }
        {
            int kk = tid >> 4, c4 = tid & 15;
            *(float4*)&Ws[kk][c4 * 4] =
                *(const float4*)&W[(k0 + kk) * Nout + n0 + c4 * 4];
        }
        __syncthreads();

        #pragma unroll
        for (int kk = 0; kk < BK; kk++) {
            float4 a4 = *(const float4*)&As[kk][ty * 4];
            ulonglong2 bb = *(const ulonglong2*)&Ws[kk][tx * 4];
            unsigned long long a0 = pack2(a4.x, a4.x);
            unsigned long long a1 = pack2(a4.y, a4.y);
            unsigned long long a2 = pack2(a4.z, a4.z);
            unsigned long long a3 = pack2(a4.w, a4.w);
            ffma2(acc2[0][0], a0, bb.x); ffma2(acc2[0][1], a0, bb.y);
            ffma2(acc2[1][0], a1, bb.x); ffma2(acc2[1][1], a1, bb.y);
            ffma2(acc2[2][0], a2, bb.x); ffma2(acc2[2][1], a2, bb.y);
            ffma2(acc2[3][0], a3, bb.x); ffma2(acc2[3][1], a3, bb.y);
        }
        __syncthreads();
    }

    float acc[4][4];
    #pragma unroll
    for (int i = 0; i < 4; i++) {
        unpack2(acc2[i][0], acc[i][0], acc[i][1]);
        unpack2(acc2[i][1], acc[i][2], acc[i][3]);
    }

    const int mb = m0 + ty * 4;
    const int nb = n0 + tx * 4;
    float4 bq = *(const float4*)&bias[nb];
    float bvv[4] = {bq.x, bq.y, bq.z, bq.w};

    if (!TRANSOUT) {
        #pragma unroll
        for (int i = 0; i < 4; i++) {
            float4 o;
            float* op = (float*)&o;
            float rr[4] = {0.f, 0.f, 0.f, 0.f};
            if (res) {
                float4 r4 = *(const float4*)&res[(mb + i) * Nout + nb];
                rr[0] = r4.x; rr[1] = r4.y; rr[2] = r4.z; rr[3] = r4.w;
            }
            #pragma unroll
            for (int j = 0; j < 4; j++) {
                float val = acc[i][j] + bvv[j];
                if (LEAKY) val = val > 0.f ? val : 0.01f * val;
                val += rr[j];
                op[j] = val;
            }
            *(float4*)&C[(mb + i) * Nout + nb] = o;
        }
    } else {
        #pragma unroll
        for (int j = 0; j < 4; j++) {
            float4 o;
            float* op = (float*)&o;
            #pragma unroll
            for (int i = 0; i < 4; i++) {
                float val = acc[i][j] + bvv[j];
                if (LEAKY) val = val > 0.f ? val : 0.01f * val;
                if (res) val += res[(mb + i) * Nout + nb + j];
                op[i] = val;
            }
            *(float4*)&C[(nb + j) * M + mb] = o;
        }
    }
}

template <bool TRANSA, bool LEAKY, bool TRANSOUT>
__global__ void __launch_bounds__(256) gemm_k(
    const float* __restrict__ A, const float* __restrict__ W,
    const float* __restrict__ bias, const float* __restrict__ res,
    float* __restrict__ C, int M, int Kd, int Nout)
{
    gemm_body<TRANSA, LEAKY, TRANSOUT>(A, W, bias, res, C, M, Kd, Nout);
}

// Fused q/k/v projection: blockIdx.z picks the triple. One launch, 216 blocks.
__global__ void __launch_bounds__(256) qkv_proj_k(
    const float* __restrict__ A0, const float* __restrict__ A1, const float* __restrict__ A2,
    const float* __restrict__ W0, const float* __restrict__ W1, const float* __restrict__ W2,
    const float* __restrict__ b0, const float* __restrict__ b1, const float* __restrict__ b2,
    float* __restrict__ C0, float* __restrict__ C1, float* __restrict__ C2)
{
    int z = blockIdx.z;
    const float* A = (z == 0) ? A0 : (z == 1) ? A1 : A2;
    const float* W = (z == 0) ? W0 : (z == 1) ? W1 : W2;
    const float* b = (z == 0) ? b0 : (z == 1) ? b1 : b2;
    float*       C = (z == 0) ? C0 : (z == 1) ? C1 : C2;
    gemm_body<true, false, false>(A, W, b, nullptr, C, NPIX, CDIM, CDIM);
}

// ---------------------------------------------------------------------------
// Cluster centers: accumulate (16 blocks x 128 threads) into g_cacc (assumed
// zero), then norm kernel computes counts from labels, writes centers, and
// RE-ZEROES g_cacc so the next graph replay starts clean.
// ---------------------------------------------------------------------------
__global__ void __launch_bounds__(128) centers_accum_k(const int* __restrict__ labels)
{
    __shared__ float sacc[NCLUST * CDIM];
    const int c = threadIdx.x;
    #pragma unroll
    for (int kk = 0; kk < NCLUST; kk++) sacc[kk * CDIM + c] = 0.f;

    const int n0 = blockIdx.x * (NPIX / 16);
    for (int n = n0; n < n0 + (NPIX / 16); n++) {
        int lab = labels[n];
        sacc[lab * CDIM + c] += g_k[n * CDIM + c];
    }
    #pragma unroll
    for (int kk = 0; kk < NCLUST; kk++)
        atomicAdd(&g_cacc[kk * CDIM + c], sacc[kk * CDIM + c]);
}

__global__ void __launch_bounds__(256) centers_norm_k(const int* __restrict__ labels)
{
    __shared__ float cnt[NCLUST];
    const int tid = threadIdx.x;
    if (tid < NCLUST) cnt[tid] = 0.f;
    __syncthreads();
    for (int n = tid; n < NPIX; n += 256)
        atomicAdd(&cnt[labels[n]], 1.f);
    __syncthreads();
    for (int t = tid; t < NCLUST * CDIM; t += 256) {
        g_centers[t] = g_cacc[t] / (cnt[t >> 7] + 1e-6f);
        g_cacc[t] = 0.f;   // self-clean for next replay
    }
}

// ---------------------------------------------------------------------------
// Attention: block = (32-query tile, head). Online softmax over 64-key tiles.
//  - inter scores: css[lab_j] * pc (elementwise, each 8-lane group owns its row)
//  - intra (same-cluster) pairs selected via 16 per-label 64-bit ballot masks,
//    processed cooperatively by the query's 8-lane group (no atomics)
//  - softmax m/l state in registers; sS/pcs rows padded to 68 floats
//    (conflict-free); PV with packed f32x2 FMA.
// ---------------------------------------------------------------------------
#define PCPAD 68

__global__ void __launch_bounds__(256) attn_k(
    const float* __restrict__ q, const float* __restrict__ k,
    const float* __restrict__ v, const float* __restrict__ centers,
    const float* __restrict__ pc, const int* __restrict__ labels,
    float* __restrict__ out)
{
    const int h   = blockIdx.y;
    const int i0  = blockIdx.x * 32;
    const int tid = threadIdx.x;
    const int qi  = tid >> 3;          // 0..31 query within tile
    const int dg  = tid & 7;           // 0..7  channel group (4 ch each)
    const int lane = tid & 31;
    const unsigned gmask = 0xFFu << (lane & 24);   // this thread's 8-lane group

    __shared__ __align__(16) float cks[16][32];
    __shared__ __align__(16) float ks[64][32];
    __shared__ __align__(16) float vs[64][32];
    __shared__ __align__(16) float pcs[32][PCPAD];
    __shared__ __align__(16) float sS[32][PCPAD];
    __shared__ float css[32][17];
    __shared__ int   labq_s[32];
    __shared__ int   labj_s[64];
    __shared__ unsigned int mlo[16], mhi[16];

    // ---- prologue: q slice to regs, centers tile, query labels ----
    float4 qreg = *(const float4*)&q[(i0 + qi) * CDIM + h * HC + dg * 4];
    if (tid < 128) {
        int kk = tid >> 3, d4 = tid & 7;
        *(float4*)&cks[kk][d4 * 4] =
            *(const float4*)&centers[kk * CDIM + h * HC + d4 * 4];
    }
    if (tid < 32) labq_s[tid] = labels[i0 + tid];
    __syncthreads();

    // center scores css[qi][kk] = q_i . center_kk (group-cooperative)
    #pragma unroll
    for (int kk = 0; kk < 16; kk++) {
        float4 c4 = *(const float4*)&cks[kk][dg * 4];
        float p = qreg.x * c4.x + qreg.y * c4.y + qreg.z * c4.z + qreg.w * c4.w;
        p += __shfl_xor_sync(gmask, p, 1);
        p += __shfl_xor_sync(gmask, p, 2);
        p += __shfl_xor_sync(gmask, p, 4);
        if (dg == 0) css[qi][kk] = p;
    }

    unsigned long long accA = 0ull, accB = 0ull;   // 4 packed fp32 accumulators
    float mi = -1e30f, li = 0.f;
    const float invScale = 0.17677669529663687f;   // 1/sqrt(32)
    const int j8 = dg * 8;

    for (int j0 = 0; j0 < NPIX; j0 += 64) {
        __syncthreads();   // previous tile fully consumed

        // ---- tile loads (all float4) ----
        #pragma unroll
        for (int t = 0; t < 2; t++) {
            int idx = tid + t * 256;          // 512 float4 for ks / vs each
            int j = idx >> 3, d4 = idx & 7;
            *(float4*)&ks[j][d4 * 4] =
                *(const float4*)&k[(j0 + j) * CDIM + h * HC + d4 * 4];
            *(float4*)&vs[j][d4 * 4] =
                *(const float4*)&v[(j0 + j) * CDIM + h * HC + d4 * 4];
        }
        #pragma unroll
        for (int t = 0; t < 2; t++) {
            int idx = tid + t * 256;          // 512 float4 for pcs
            int qq = idx >> 4, j4 = idx & 15;
            *(float4*)&pcs[qq][j4 * 4] =
                *(const float4*)&pc[(i0 + qq) * NPIX + j0 + j4 * 4];
        }
        if (tid < 64) {
            int lj = labels[j0 + tid];
            labj_s[tid] = lj;
            // per-label 64-bit membership masks via ballots (warps 0 and 1)
            #pragma unroll
            for (int L = 0; L < NCLUST; L++) {
                unsigned b = __ballot_sync(0xffffffffu, lj == L);
                if (lane == 0) {
                    if (tid < 32) mlo[L] = b; else mhi[L] = b;
                }
            }
        }
        __syncthreads();

        const int Lq = labq_s[qi];

        // ---- inter scores: own 8 columns ----
        {
            float4 pA = *(const float4*)&pcs[qi][j8];
            float4 pB = *(const float4*)&pcs[qi][j8 + 4];
            float4 oA, oB;
            oA.x = css[qi][labj_s[j8 + 0]] * pA.x * invScale;
            oA.y = css[qi][labj_s[j8 + 1]] * pA.y * invScale;
            oA.z = css[qi][labj_s[j8 + 2]] * pA.z * invScale;
            oA.w = css[qi][labj_s[j8 + 3]] * pA.w * invScale;
            oB.x = css[qi][labj_s[j8 + 4]] * pB.x * invScale;
            oB.y = css[qi][labj_s[j8 + 5]] * pB.y * invScale;
            oB.z = css[qi][labj_s[j8 + 6]] * pB.z * invScale;
            oB.w = css[qi][labj_s[j8 + 7]] * pB.w * invScale;
            *(float4*)&sS[qi][j8]     = oA;
            *(float4*)&sS[qi][j8 + 4] = oB;
        }

        // ---- intra (same-cluster) overwrites: group-cooperative dot32 ----
        {
            unsigned long long m =
                ((unsigned long long)mhi[Lq] << 32) | (unsigned long long)mlo[Lq];
            while (m) {
                int j = __ffsll((long long)m) - 1;
                m &= m - 1;
                float4 k4 = *(const float4*)&ks[j][dg * 4];
                float p = qreg.x * k4.x + qreg.y * k4.y +
                          qreg.z * k4.z + qreg.w * k4.w;
                p += __shfl_xor_sync(gmask, p, 1);
                p += __shfl_xor_sync(gmask, p, 2);
                p += __shfl_xor_sync(gmask, p, 4);
                if (dg == 0) sS[qi][j] = p * invScale;
            }
        }
        __syncwarp();

        // ---- online softmax (registers + group shuffles) ----
        float4 sA = *(const float4*)&sS[qi][j8];
        float4 sB = *(const float4*)&sS[qi][j8 + 4];
        float mloc = fmaxf(fmaxf(fmaxf(sA.x, sA.y), fmaxf(sA.z, sA.w)),
                           fmaxf(fmaxf(sB.x, sB.y), fmaxf(sB.z, sB.w)));
        mloc = fmaxf(mloc, __shfl_xor_sync(gmask, mloc, 1));
        mloc = fmaxf(mloc, __shfl_xor_sync(gmask, mloc, 2));
        mloc = fmaxf(mloc, __shfl_xor_sync(gmask, mloc, 4));
        float mnew   = fmaxf(mi, mloc);
        float factor = __expf(mi - mnew);
        sA.x = __expf(sA.x - mnew); sA.y = __expf(sA.y - mnew);
        sA.z = __expf(sA.z - mnew); sA.w = __expf(sA.w - mnew);
        sB.x = __expf(sB.x - mnew); sB.y = __expf(sB.y - mnew);
        sB.z = __expf(sB.z - mnew); sB.w = __expf(sB.w - mnew);
        float psum = (sA.x + sA.y) + (sA.z + sA.w) +
                     (sB.x + sB.y) + (sB.z + sB.w);
        *(float4*)&sS[qi][j8]     = sA;
        *(float4*)&sS[qi][j8 + 4] = sB;
        psum += __shfl_xor_sync(gmask, psum, 1);
        psum += __shfl_xor_sync(gmask, psum, 2);
        psum += __shfl_xor_sync(gmask, psum, 4);
        li = li * factor + psum;
        mi = mnew;
        __syncwarp();

        // ---- PV accumulate (packed f32x2) ----
        {
            unsigned long long ff = pack2(factor, factor);
            accA = mul2(accA, ff);
            accB = mul2(accB, ff);
        }
        #pragma unroll 8
        for (int j4 = 0; j4 < 16; j4++) {
            float4 p4 = *(const float4*)&sS[qi][j4 * 4];
            {
                ulonglong2 vv = *(const ulonglong2*)&vs[j4 * 4 + 0][dg * 4];
                unsigned long long pp = pack2(p4.x, p4.x);
                ffma2(accA, pp, vv.x); ffma2(accB, pp, vv.y);
            }
            {
                ulonglong2 vv = *(const ulonglong2*)&vs[j4 * 4 + 1][dg * 4];
                unsigned long long pp = pack2(p4.y, p4.y);
                ffma2(accA, pp, vv.x); ffma2(accB, pp, vv.y);
            }
            {
                ulonglong2 vv = *(const ulonglong2*)&vs[j4 * 4 + 2][dg * 4];
                unsigned long long pp = pack2(p4.z, p4.z);
                ffma2(accA, pp, vv.x); ffma2(accB, pp, vv.y);
            }
            {
                ulonglong2 vv = *(const ulonglong2*)&vs[j4 * 4 + 3][dg * 4];
                unsigned long long pp = pack2(p4.w, p4.w);
                ffma2(accA, pp, vv.x); ffma2(accB, pp, vv.y);
            }
        }
    }

    // ---- epilogue ----
    float linv = 1.0f / li;
    float4 o;
    unpack2(accA, o.x, o.y);
    unpack2(accB, o.z, o.w);
    o.x *= linv; o.y *= linv; o.z *= linv; o.w *= linv;
    *(float4*)&out[(i0 + qi) * CDIM + h * HC + dg * 4] = o;
}

// ---------------------------------------------------------------------------
// Host orchestration (8 launches)
// ---------------------------------------------------------------------------
extern "C" void kernel_launch(void* const* d_in, const int* in_sizes, int n_in,
                              void* d_out, int out_size)
{
    // Input order detection: dict order has labels (2304 ints) at index 4;
    // signature order puts labels last (index 18).
    const bool dictOrder = (in_sizes[4] == NPIX);
    const int wb = dictOrder ? 5 : 4;

    const float* q_img = (const float*)d_in[0];
    const float* k_img = (const float*)d_in[1];
    const float* v_img = (const float*)d_in[2];
    const float* pc    = (const float*)d_in[3];
    const int*   labels = (const int*)d_in[dictOrder ? 4 : 18];

    const float* wq  = (const float*)d_in[wb + 0];
    const float* bq  = (const float*)d_in[wb + 1];
    const float* wk  = (const float*)d_in[wb + 2];
    const float* bk  = (const float*)d_in[wb + 3];
    const float* wv  = (const float*)d_in[wb + 4];
    const float* bv  = (const float*)d_in[wb + 5];
    const float* w1a = (const float*)d_in[wb + 6];
    const float* b1a = (const float*)d_in[wb + 7];
    const float* w1b = (const float*)d_in[wb + 8];
    const float* b1b = (const float*)d_in[wb + 9];
    const float* w2a = (const float*)d_in[wb + 10];
    const float* b2a = (const float*)d_in[wb + 11];
    const float* w2b = (const float*)d_in[wb + 12];
    const float* b2b = (const float*)d_in[wb + 13];
    float* out = (float*)d_out;

    void* p;
    cudaGetSymbolAddress(&p, g_q);       float* pq  = (float*)p;
    cudaGetSymbolAddress(&p, g_k);       float* pk  = (float*)p;
    cudaGetSymbolAddress(&p, g_v);       float* pv  = (float*)p;
    cudaGetSymbolAddress(&p, g_centers); float* pce = (float*)p;
    cudaGetSymbolAddress(&p, g_attn);    float* pat = (float*)p;
    cudaGetSymbolAddress(&p, g_h1);      float* ph1 = (float*)p;
    cudaGetSymbolAddress(&p, g_rs1);     float* pr1 = (float*)p;
    cudaGetSymbolAddress(&p, g_h2);      float* ph2 = (float*)p;

    dim3 blk(256);
    dim3 gProj(CDIM / BN, NPIX / BM);        // (2, 36)
    dim3 gHid(HID / BN, NPIX / BM);          // (4, 36)
    dim3 gQKV(CDIM / BN, NPIX / BM, 3);      // (2, 36, 3) fused projections

    // fused q/k/v projections (img is channel-major -> TRANSA read)
    qkv_proj_k<<<gQKV, blk>>>(q_img, k_img, v_img, wq, wk, wv,
                              bq, bk, bv, pq, pk, pv);

    // cluster centers from projected k (g_cacc enters zeroed; norm re-zeroes)
    centers_accum_k<<<16, 128>>>(labels);
    centers_norm_k<<<1, 256>>>(labels);

    // attention
    attn_k<<<dim3(NPIX / 32, NH), blk>>>(pq, pk, pv, pce, pc, labels, pat);

    // mlp_1 with residual v, mlp_2 with residual rs1 (transposed final write)
    gemm_k<false, true,  false><<<gHid,  blk>>>(pat, w1a, b1a, nullptr, ph1, NPIX, CDIM, HID);
    gemm_k<false, false, false><<<gProj, blk>>>(ph1, w1b, b1b, pv,      pr1, NPIX, HID, CDIM);
    gemm_k<false, true,  false><<<gHid,  blk>>>(pr1, w2a, b2a, nullptr, ph2, NPIX, CDIM, HID);
    gemm_k<false, false, true ><<<gProj, blk>>>(ph2, w2b, b2b, pr1,     out, NPIX, HID, CDIM);
}

// round 8
// speedup vs baseline: 1.1067x; 1.0417x over previous
#include <cuda_runtime.h>
#include <cuda_bf16.h>

// ---------------------------------------------------------------------------
// Problem constants
// ---------------------------------------------------------------------------
#define NPIX 2304      // N = 48*48
#define CDIM 128       // channels
#define NH   4         // heads
#define HC   32        // head channels
#define NCLUST 16      // clusters
#define HID  256       // mlp hidden = 2C

#define NSPLIT 3       // key-dimension split for attention
#define JLEN (NPIX / NSPLIT)   // 768 keys per split

// ---------------------------------------------------------------------------
// Packed fp32x2 helpers (sm_100+: fma.rn.f32x2 — exact fp32 arithmetic)
// ---------------------------------------------------------------------------
__device__ __forceinline__ unsigned long long pack2(float x, float y) {
    unsigned long long r;
    asm("mov.b64 %0, {%1, %2};" : "=l"(r) : "f"(x), "f"(y));
    return r;
}
__device__ __forceinline__ void unpack2(unsigned long long v, float& x, float& y) {
    asm("mov.b64 {%0, %1}, %2;" : "=f"(x), "=f"(y) : "l"(v));
}
__device__ __forceinline__ void ffma2(unsigned long long& d,
                                      unsigned long long a, unsigned long long b) {
    asm("fma.rn.f32x2 %0, %1, %2, %0;" : "+l"(d) : "l"(a), "l"(b));
}
__device__ __forceinline__ unsigned long long mul2(unsigned long long a,
                                                   unsigned long long b) {
    unsigned long long r;
    asm("mul.rn.f32x2 %0, %1, %2;" : "=l"(r) : "l"(a), "l"(b));
    return r;
}

// ---------------------------------------------------------------------------
// Device scratch (allocation-free rule: __device__ globals; zero at load)
// ---------------------------------------------------------------------------
__device__ float g_q[NPIX * CDIM];
__device__ float g_k[NPIX * CDIM];
__device__ float g_v[NPIX * CDIM];
__device__ float g_cacc[NCLUST * CDIM];   // zero at entry; norm re-zeroes
__device__ float g_centers[NCLUST * CDIM];
__device__ float g_attn[NPIX * CDIM];
__device__ float g_h1[NPIX * HID];
__device__ float g_rs1[NPIX * CDIM];
__device__ float g_h2[NPIX * HID];
__device__ float g_pacc[NSPLIT * NPIX * CDIM];       // split partial PV accs
__device__ float g_pml[NSPLIT * NH * NPIX * 2];      // split partial (m, l)

// ---------------------------------------------------------------------------
// Tiled GEMM body:  C = act(A @ W + b) (+ res); BM=32, BN=64, BK=16,
// 256 threads, 2x4 microtile, f32x2 packed FMA inner loop.
// BM=32 doubles block count vs BM=64 -> much better chip fill (144/288 blocks).
// ---------------------------------------------------------------------------
#define BM 32
#define BN 64
#define BK 16

template <bool TRANSA, bool LEAKY, bool TRANSOUT>
__device__ __forceinline__ void gemm_body(
    const float* __restrict__ A, const float* __restrict__ W,
    const float* __restrict__ bias, const float* __restrict__ res,
    float* __restrict__ C, int M, int Kd, int Nout)
{
    __shared__ __align__(16) float As[BK][BM + 4];
    __shared__ __align__(16) float Ws[BK][BN + 4];

    const int tid = threadIdx.x;
    const int tx = tid & 15;   // -> n (4 cols each)
    const int ty = tid >> 4;   // -> m (2 rows each), 0..15
    const int m0 = blockIdx.y * BM;
    const int n0 = blockIdx.x * BN;

    unsigned long long acc2[2][2] = {};   // 2 rows x (2 packed pairs)

    for (int k0 = 0; k0 < Kd; k0 += BK) {
        if (TRANSA) {
            // A stored [K][M]: row kk has contiguous m — 8 float4 per kk row
            if (tid < 128) {
                int kk = tid >> 3, r4 = tid & 7;
                *(float4*)&As[kk][r4 * 4] =
                    *(const float4*)&A[(k0 + kk) * M + m0 + r4 * 4];
            }
        } else {
            // A stored [M][K]: contiguous kk — float4 load, scattered store
            if (tid < 128) {
                int r = tid & 31, kq = tid >> 5;   // kq 0..3
                float4 g = *(const float4*)&A[(m0 + r) * Kd + k0 + kq * 4];
                As[kq * 4 + 0][r] = g.x;
                As[kq * 4 + 1][r] = g.y;
                As[kq * 4 + 2][r] = g.z;
                As[kq * 4 + 3][r] = g.w;
            }
        }
        {
            int kk = tid >> 4, c4 = tid & 15;
            *(float4*)&Ws[kk][c4 * 4] =
                *(const float4*)&W[(k0 + kk) * Nout + n0 + c4 * 4];
        }
        __syncthreads();

        #pragma unroll
        for (int kk = 0; kk < BK; kk++) {
            float2 a2 = *(const float2*)&As[kk][ty * 2];
            ulonglong2 bb = *(const ulonglong2*)&Ws[kk][tx * 4];
            unsigned long long a0 = pack2(a2.x, a2.x);
            unsigned long long a1 = pack2(a2.y, a2.y);
            ffma2(acc2[0][0], a0, bb.x); ffma2(acc2[0][1], a0, bb.y);
            ffma2(acc2[1][0], a1, bb.x); ffma2(acc2[1][1], a1, bb.y);
        }
        __syncthreads();
    }

    float acc[2][4];
    #pragma unroll
    for (int i = 0; i < 2; i++) {
        unpack2(acc2[i][0], acc[i][0], acc[i][1]);
        unpack2(acc2[i][1], acc[i][2], acc[i][3]);
    }

    const int mb = m0 + ty * 2;
    const int nb = n0 + tx * 4;
    float4 bq = *(const float4*)&bias[nb];
    float bvv[4] = {bq.x, bq.y, bq.z, bq.w};

    if (!TRANSOUT) {
        #pragma unroll
        for (int i = 0; i < 2; i++) {
            float4 o;
            float* op = (float*)&o;
            float rr[4] = {0.f, 0.f, 0.f, 0.f};
            if (res) {
                float4 r4 = *(const float4*)&res[(mb + i) * Nout + nb];
                rr[0] = r4.x; rr[1] = r4.y; rr[2] = r4.z; rr[3] = r4.w;
            }
            #pragma unroll
            for (int j = 0; j < 4; j++) {
                float val = acc[i][j] + bvv[j];
                if (LEAKY) val = val > 0.f ? val : 0.01f * val;
                val += rr[j];
                op[j] = val;
            }
            *(float4*)&C[(mb + i) * Nout + nb] = o;
        }
    } else {
        #pragma unroll
        for (int j = 0; j < 4; j++) {
            float2 o;
            float* op = (float*)&o;
            #pragma unroll
            for (int i = 0; i < 2; i++) {
                float val = acc[i][j] + bvv[j];
                if (LEAKY) val = val > 0.f ? val : 0.01f * val;
                if (res) val += res[(mb + i) * Nout + nb + j];
                op[i] = val;
            }
            *(float2*)&C[(nb + j) * M + mb] = o;
        }
    }
}

template <bool TRANSA, bool LEAKY, bool TRANSOUT>
__global__ void __launch_bounds__(256) gemm_k(
    const float* __restrict__ A, const float* __restrict__ W,
    const float* __restrict__ bias, const float* __restrict__ res,
    float* __restrict__ C, int M, int Kd, int Nout)
{
    gemm_body<TRANSA, LEAKY, TRANSOUT>(A, W, bias, res, C, M, Kd, Nout);
}

// Fused q/k/v projection: blockIdx.z picks the triple. One launch, 432 blocks.
__global__ void __launch_bounds__(256) qkv_proj_k(
    const float* __restrict__ A0, const float* __restrict__ A1, const float* __restrict__ A2,
    const float* __restrict__ W0, const float* __restrict__ W1, const float* __restrict__ W2,
    const float* __restrict__ b0, const float* __restrict__ b1, const float* __restrict__ b2,
    float* __restrict__ C0, float* __restrict__ C1, float* __restrict__ C2)
{
    int z = blockIdx.z;
    const float* A = (z == 0) ? A0 : (z == 1) ? A1 : A2;
    const float* W = (z == 0) ? W0 : (z == 1) ? W1 : W2;
    const float* b = (z == 0) ? b0 : (z == 1) ? b1 : b2;
    float*       C = (z == 0) ? C0 : (z == 1) ? C1 : C2;
    gemm_body<true, false, false>(A, W, b, nullptr, C, NPIX, CDIM, CDIM);
}

// ---------------------------------------------------------------------------
// Cluster centers
// ---------------------------------------------------------------------------
__global__ void __launch_bounds__(128) centers_accum_k(const int* __restrict__ labels)
{
    __shared__ float sacc[NCLUST * CDIM];
    const int c = threadIdx.x;
    #pragma unroll
    for (int kk = 0; kk < NCLUST; kk++) sacc[kk * CDIM + c] = 0.f;

    const int n0 = blockIdx.x * (NPIX / 16);
    for (int n = n0; n < n0 + (NPIX / 16); n++) {
        int lab = labels[n];
        sacc[lab * CDIM + c] += g_k[n * CDIM + c];
    }
    #pragma unroll
    for (int kk = 0; kk < NCLUST; kk++)
        atomicAdd(&g_cacc[kk * CDIM + c], sacc[kk * CDIM + c]);
}

__global__ void __launch_bounds__(256) centers_norm_k(const int* __restrict__ labels)
{
    __shared__ float cnt[NCLUST];
    const int tid = threadIdx.x;
    if (tid < NCLUST) cnt[tid] = 0.f;
    __syncthreads();
    for (int n = tid; n < NPIX; n += 256)
        atomicAdd(&cnt[labels[n]], 1.f);
    __syncthreads();
    for (int t = tid; t < NCLUST * CDIM; t += 256) {
        g_centers[t] = g_cacc[t] / (cnt[t >> 7] + 1e-6f);
        g_cacc[t] = 0.f;   // self-clean for next replay
    }
}

// ---------------------------------------------------------------------------
// Attention, split-K over keys: block = (32-query tile, head, split).
// Each block runs online softmax over its 768-key range and writes the
// UNNORMALIZED accumulator plus (m, l) partials; merge_k combines splits.
//  - pc read straight from global into regs (overlaps the tile barrier)
//  - intra pairs via 16 per-label 64-bit ballot masks (no atomics)
//  - sS rows padded to 68 (conflict-free); PV with packed f32x2 FMA.
// ---------------------------------------------------------------------------
#define PCPAD 68

__global__ void __launch_bounds__(256, 5) attn_k(
    const float* __restrict__ q, const float* __restrict__ k,
    const float* __restrict__ v, const float* __restrict__ centers,
    const float* __restrict__ pc, const int* __restrict__ labels,
    float* __restrict__ pacc, float* __restrict__ pml)
{
    const int h   = blockIdx.y;
    const int i0  = blockIdx.x * 32;
    const int s   = blockIdx.z;
    const int jbeg = s * JLEN;
    const int tid = threadIdx.x;
    const int qi  = tid >> 3;          // 0..31 query within tile
    const int dg  = tid & 7;           // 0..7  channel group (4 ch each)
    const int lane = tid & 31;
    const unsigned gmask = 0xFFu << (lane & 24);   // this thread's 8-lane group

    __shared__ __align__(16) float cks[16][32];
    __shared__ __align__(16) float ks[64][32];
    __shared__ __align__(16) float vs[64][32];
    __shared__ __align__(16) float sS[32][PCPAD];
    __shared__ float css[32][17];
    __shared__ int   labq_s[32];
    __shared__ int   labj_s[64];
    __shared__ unsigned int mlo[16], mhi[16];

    // ---- prologue: q slice to regs, centers tile, query labels ----
    float4 qreg = *(const float4*)&q[(i0 + qi) * CDIM + h * HC + dg * 4];
    if (tid < 128) {
        int kk = tid >> 3, d4 = tid & 7;
        *(float4*)&cks[kk][d4 * 4] =
            *(const float4*)&centers[kk * CDIM + h * HC + d4 * 4];
    }
    if (tid < 32) labq_s[tid] = labels[i0 + tid];
    __syncthreads();

    // center scores css[qi][kk] = q_i . center_kk (group-cooperative)
    #pragma unroll
    for (int kk = 0; kk < 16; kk++) {
        float4 c4 = *(const float4*)&cks[kk][dg * 4];
        float p = qreg.x * c4.x + qreg.y * c4.y + qreg.z * c4.z + qreg.w * c4.w;
        p += __shfl_xor_sync(gmask, p, 1);
        p += __shfl_xor_sync(gmask, p, 2);
        p += __shfl_xor_sync(gmask, p, 4);
        if (dg == 0) css[qi][kk] = p;
    }

    unsigned long long accA = 0ull, accB = 0ull;   // 4 packed fp32 accumulators
    float mi = -1e30f, li = 0.f;
    const float invScale = 0.17677669529663687f;   // 1/sqrt(32)
    const int j8 = dg * 8;

    for (int j0 = jbeg; j0 < jbeg + JLEN; j0 += 64) {
        __syncthreads();   // previous tile fully consumed

        // ---- k/v tile loads (all float4) ----
        #pragma unroll
        for (int t = 0; t < 2; t++) {
            int idx = tid + t * 256;          // 512 float4 for ks / vs each
            int j = idx >> 3, d4 = idx & 7;
            *(float4*)&ks[j][d4 * 4] =
                *(const float4*)&k[(j0 + j) * CDIM + h * HC + d4 * 4];
            *(float4*)&vs[j][d4 * 4] =
                *(const float4*)&v[(j0 + j) * CDIM + h * HC + d4 * 4];
        }
        // pc straight into registers: latency overlaps the barrier below
        float4 pA = *(const float4*)&pc[(i0 + qi) * NPIX + j0 + j8];
        float4 pB = *(const float4*)&pc[(i0 + qi) * NPIX + j0 + j8 + 4];

        if (tid < 64) {
            int lj = labels[j0 + tid];
            labj_s[tid] = lj;
            // per-label 64-bit membership masks via ballots (warps 0 and 1)
            #pragma unroll
            for (int L = 0; L < NCLUST; L++) {
                unsigned b = __ballot_sync(0xffffffffu, lj == L);
                if (lane == 0) {
                    if (tid < 32) mlo[L] = b; else mhi[L] = b;
                }
            }
        }
        __syncthreads();

        const int Lq = labq_s[qi];

        // ---- inter scores: own 8 columns ----
        {
            float4 oA, oB;
            oA.x = css[qi][labj_s[j8 + 0]] * pA.x * invScale;
            oA.y = css[qi][labj_s[j8 + 1]] * pA.y * invScale;
            oA.z = css[qi][labj_s[j8 + 2]] * pA.z * invScale;
            oA.w = css[qi][labj_s[j8 + 3]] * pA.w * invScale;
            oB.x = css[qi][labj_s[j8 + 4]] * pB.x * invScale;
            oB.y = css[qi][labj_s[j8 + 5]] * pB.y * invScale;
            oB.z = css[qi][labj_s[j8 + 6]] * pB.z * invScale;
            oB.w = css[qi][labj_s[j8 + 7]] * pB.w * invScale;
            *(float4*)&sS[qi][j8]     = oA;
            *(float4*)&sS[qi][j8 + 4] = oB;
        }

        // ---- intra (same-cluster) overwrites: group-cooperative dot32 ----
        {
            unsigned long long m =
                ((unsigned long long)mhi[Lq] << 32) | (unsigned long long)mlo[Lq];
            while (m) {
                int j = __ffsll((long long)m) - 1;
                m &= m - 1;
                float4 k4 = *(const float4*)&ks[j][dg * 4];
                float p = qreg.x * k4.x + qreg.y * k4.y +
                          qreg.z * k4.z + qreg.w * k4.w;
                p += __shfl_xor_sync(gmask, p, 1);
                p += __shfl_xor_sync(gmask, p, 2);
                p += __shfl_xor_sync(gmask, p, 4);
                if (dg == 0) sS[qi][j] = p * invScale;
            }
        }
        __syncwarp();

        // ---- online softmax (registers + group shuffles) ----
        float4 sA = *(const float4*)&sS[qi][j8];
        float4 sB = *(const float4*)&sS[qi][j8 + 4];
        float mloc = fmaxf(fmaxf(fmaxf(sA.x, sA.y), fmaxf(sA.z, sA.w)),
                           fmaxf(fmaxf(sB.x, sB.y), fmaxf(sB.z, sB.w)));
        mloc = fmaxf(mloc, __shfl_xor_sync(gmask, mloc, 1));
        mloc = fmaxf(mloc, __shfl_xor_sync(gmask, mloc, 2));
        mloc = fmaxf(mloc, __shfl_xor_sync(gmask, mloc, 4));
        float mnew   = fmaxf(mi, mloc);
        float factor = __expf(mi - mnew);
        sA.x = __expf(sA.x - mnew); sA.y = __expf(sA.y - mnew);
        sA.z = __expf(sA.z - mnew); sA.w = __expf(sA.w - mnew);
        sB.x = __expf(sB.x - mnew); sB.y = __expf(sB.y - mnew);
        sB.z = __expf(sB.z - mnew); sB.w = __expf(sB.w - mnew);
        float psum = (sA.x + sA.y) + (sA.z + sA.w) +
                     (sB.x + sB.y) + (sB.z + sB.w);
        *(float4*)&sS[qi][j8]     = sA;
        *(float4*)&sS[qi][j8 + 4] = sB;
        psum += __shfl_xor_sync(gmask, psum, 1);
        psum += __shfl_xor_sync(gmask, psum, 2);
        psum += __shfl_xor_sync(gmask, psum, 4);
        li = li * factor + psum;
        mi = mnew;
        __syncwarp();

        // ---- PV accumulate (packed f32x2) ----
        {
            unsigned long long ff = pack2(factor, factor);
            accA = mul2(accA, ff);
            accB = mul2(accB, ff);
        }
        #pragma unroll 8
        for (int j4 = 0; j4 < 16; j4++) {
            float4 p4 = *(const float4*)&sS[qi][j4 * 4];
            {
                ulonglong2 vv = *(const ulonglong2*)&vs[j4 * 4 + 0][dg * 4];
                unsigned long long pp = pack2(p4.x, p4.x);
                ffma2(accA, pp, vv.x); ffma2(accB, pp, vv.y);
            }
            {
                ulonglong2 vv = *(const ulonglong2*)&vs[j4 * 4 + 1][dg * 4];
                unsigned long long pp = pack2(p4.y, p4.y);
                ffma2(accA, pp, vv.x); ffma2(accB, pp, vv.y);
            }
            {
                ulonglong2 vv = *(const ulonglong2*)&vs[j4 * 4 + 2][dg * 4];
                unsigned long long pp = pack2(p4.z, p4.z);
                ffma2(accA, pp, vv.x); ffma2(accB, pp, vv.y);
            }
            {
                ulonglong2 vv = *(const ulonglong2*)&vs[j4 * 4 + 3][dg * 4];
                unsigned long long pp = pack2(p4.w, p4.w);
                ffma2(accA, pp, vv.x); ffma2(accB, pp, vv.y);
            }
        }
    }

    // ---- epilogue: UNNORMALIZED partial + (m, l) ----
    float4 o;
    unpack2(accA, o.x, o.y);
    unpack2(accB, o.z, o.w);
    *(float4*)&pacc[(s * NPIX + i0 + qi) * CDIM + h * HC + dg * 4] = o;
    if (dg == 0) {
        float2 ml = {mi, li};
        ((float2*)pml)[(s * NH + h) * NPIX + i0 + qi] = ml;
    }
}

// ---------------------------------------------------------------------------
// Merge splits: out = sum_s e^{m_s - M} acc_s / sum_s e^{m_s - M} l_s
// One thread per float4 of output (73728 threads).
// ---------------------------------------------------------------------------
__global__ void __launch_bounds__(256) merge_k(
    const float* __restrict__ pacc, const float* __restrict__ pml,
    float* __restrict__ out)
{
    int idx = blockIdx.x * 256 + threadIdx.x;   // 0..(NPIX*32-1)
    int pix = idx >> 5;
    int cg  = idx & 31;            // float4 index within the 128-ch row
    int h   = cg >> 3;

    const float2* ml = (const float2*)pml;
    float2 ml0 = ml[(0 * NH + h) * NPIX + pix];
    float2 ml1 = ml[(1 * NH + h) * NPIX + pix];
    float2 ml2 = ml[(2 * NH + h) * NPIX + pix];
    float M = fmaxf(ml0.x, fmaxf(ml1.x, ml2.x));
    float w0 = __expf(ml0.x - M);
    float w1 = __expf(ml1.x - M);
    float w2 = __expf(ml2.x - M);
    float den = w0 * ml0.y + w1 * ml1.y + w2 * ml2.y;
    float inv = 1.0f / den;

    const float4* pa = (const float4*)pacc;
    float4 a0 = pa[(0 * NPIX + pix) * 32 + cg];
    float4 a1 = pa[(1 * NPIX + pix) * 32 + cg];
    float4 a2 = pa[(2 * NPIX + pix) * 32 + cg];
    float4 o;
    o.x = (w0 * a0.x + w1 * a1.x + w2 * a2.x) * inv;
    o.y = (w0 * a0.y + w1 * a1.y + w2 * a2.y) * inv;
    o.z = (w0 * a0.z + w1 * a1.z + w2 * a2.z) * inv;
    o.w = (w0 * a0.w + w1 * a1.w + w2 * a2.w) * inv;
    ((float4*)out)[pix * 32 + cg] = o;
}

// ---------------------------------------------------------------------------
// Host orchestration (9 launches)
// ---------------------------------------------------------------------------
extern "C" void kernel_launch(void* const* d_in, const int* in_sizes, int n_in,
                              void* d_out, int out_size)
{
    // Input order detection: dict order has labels (2304 ints) at index 4;
    // signature order puts labels last (index 18).
    const bool dictOrder = (in_sizes[4] == NPIX);
    const int wb = dictOrder ? 5 : 4;

    const float* q_img = (const float*)d_in[0];
    const float* k_img = (const float*)d_in[1];
    const float* v_img = (const float*)d_in[2];
    const float* pc    = (const float*)d_in[3];
    const int*   labels = (const int*)d_in[dictOrder ? 4 : 18];

    const float* wq  = (const float*)d_in[wb + 0];
    const float* bq  = (const float*)d_in[wb + 1];
    const float* wk  = (const float*)d_in[wb + 2];
    const float* bk  = (const float*)d_in[wb + 3];
    const float* wv  = (const float*)d_in[wb + 4];
    const float* bv  = (const float*)d_in[wb + 5];
    const float* w1a = (const float*)d_in[wb + 6];
    const float* b1a = (const float*)d_in[wb + 7];
    const float* w1b = (const float*)d_in[wb + 8];
    const float* b1b = (const float*)d_in[wb + 9];
    const float* w2a = (const float*)d_in[wb + 10];
    const float* b2a = (const float*)d_in[wb + 11];
    const float* w2b = (const float*)d_in[wb + 12];
    const float* b2b = (const float*)d_in[wb + 13];
    float* out = (float*)d_out;

    void* p;
    cudaGetSymbolAddress(&p, g_q);       float* pq   = (float*)p;
    cudaGetSymbolAddress(&p, g_k);       float* pk   = (float*)p;
    cudaGetSymbolAddress(&p, g_v);       float* pv   = (float*)p;
    cudaGetSymbolAddress(&p, g_centers); float* pce  = (float*)p;
    cudaGetSymbolAddress(&p, g_attn);    float* pat  = (float*)p;
    cudaGetSymbolAddress(&p, g_h1);      float* ph1  = (float*)p;
    cudaGetSymbolAddress(&p, g_rs1);     float* pr1  = (float*)p;
    cudaGetSymbolAddress(&p, g_h2);      float* ph2  = (float*)p;
    cudaGetSymbolAddress(&p, g_pacc);    float* ppa  = (float*)p;
    cudaGetSymbolAddress(&p, g_pml);     float* ppml = (float*)p;

    dim3 blk(256);
    dim3 gProj(CDIM / BN, NPIX / BM);        // (2, 72)
    dim3 gHid(HID / BN, NPIX / BM);          // (4, 72)
    dim3 gQKV(CDIM / BN, NPIX / BM, 3);      // (2, 72, 3) fused projections

    // fused q/k/v projections (img is channel-major -> TRANSA read)
    qkv_proj_k<<<gQKV, blk>>>(q_img, k_img, v_img, wq, wk, wv,
                              bq, bk, bv, pq, pk, pv);

    // cluster centers from projected k (g_cacc enters zeroed; norm re-zeroes)
    centers_accum_k<<<16, 128>>>(labels);
    centers_norm_k<<<1, 256>>>(labels);

    // attention: split-K over keys, then merge
    attn_k<<<dim3(NPIX / 32, NH, NSPLIT), blk>>>(pq, pk, pv, pce, pc, labels,
                                                 ppa, ppml);
    merge_k<<<(NPIX * 32) / 256, blk>>>(ppa, ppml, pat);

    // mlp_1 with residual v, mlp_2 with residual rs1 (transposed final write)
    gemm_k<false, true,  false><<<gHid,  blk>>>(pat, w1a, b1a, nullptr, ph1, NPIX, CDIM, HID);
    gemm_k<false, false, false><<<gProj, blk>>>(ph1, w1b, b1b, pv,      pr1, NPIX, HID, CDIM);
    gemm_k<false, true,  false><<<gHid,  blk>>>(pr1, w2a, b2a, nullptr, ph2, NPIX, CDIM, HID);
    gemm_k<false, false, true ><<<gProj, blk>>>(ph2, w2b, b2b, pr1,     out, NPIX, HID, CDIM);
}